// round 4
// baseline (speedup 1.0000x reference)
#include <cuda_runtime.h>
#include <cuda_bf16.h>
#include <math.h>
#include <float.h>
#include <stdint.h>

#define CH    64
#define IMG_W 256
#define IMG_H 256
#define HWN   65536
#define NB    8

// ---------------- scratch (device globals; 16B-aligned for vector ld/st) ----
__device__ __align__(16) float g_r1[NB * CH * HWN];
__device__ __align__(16) float g_r [NB * CH * HWN];
__device__ __align__(16) float g_avg[NB * HWN];
__device__ __align__(16) float g_max[NB * HWN];
__device__ __align__(16) float g_sg [NB * HWN];
__device__ float g_chansum[NB * CH];
__device__ __align__(16) __nv_bfloat16 g_Kpk[NB * 2 * 64 * 128];   // [b][set*64+oc][ch-hi|ch-lo]
__device__ __align__(16) __nv_bfloat16 g_Wpack[2 * 9 * 2 * 64 * 64];

__device__ __forceinline__ int reflect(int v, int n) {
    if (v < 0) v = -v;
    if (v >= n) v = 2 * n - 2 - v;
    return v;
}
__device__ __forceinline__ uint32_t s2u(const void* p) {
    return (uint32_t)__cvta_generic_to_shared(p);
}
__device__ __forceinline__ void ldsm_x4(uint32_t addr, uint32_t& r0, uint32_t& r1,
                                        uint32_t& r2, uint32_t& r3) {
    asm volatile("ldmatrix.sync.aligned.m8n8.x4.shared.b16 {%0,%1,%2,%3}, [%4];"
                 : "=r"(r0), "=r"(r1), "=r"(r2), "=r"(r3) : "r"(addr));
}
__device__ __forceinline__ void mma16816(float* c, const uint32_t* a,
                                         uint32_t b0, uint32_t b1) {
    asm volatile("mma.sync.aligned.m16n8k16.row.col.f32.bf16.bf16.f32 "
                 "{%0,%1,%2,%3}, {%4,%5,%6,%7}, {%8,%9}, {%0,%1,%2,%3};"
                 : "+f"(c[0]), "+f"(c[1]), "+f"(c[2]), "+f"(c[3])
                 : "r"(a[0]), "r"(a[1]), "r"(a[2]), "r"(a[3]), "r"(b0), "r"(b1));
}

// ---------------- init ----------------
__global__ void init_kernel() {
    int i = blockIdx.x * blockDim.x + threadIdx.x;
    if (i < NB * CH) g_chansum[i] = 0.0f;
}

// ---------------- weight prepack: fp32 OIHW -> bf16 hi/lo, [cv][tap][chunk][oc][64]
__global__ __launch_bounds__(256)
void wpack_kernel(const float* __restrict__ w1, const float* __restrict__ w2) {
    int idx = blockIdx.x * 256 + threadIdx.x;       // < 73728
    if (idx >= 73728) return;
    int ch5 = idx & 31;
    int r   = idx >> 5;        // (((cv*9+t)*2+c2)*64 + oc)
    int oc  = r & 63;
    int r2  = r >> 6;
    int c2  = r2 & 1;
    int r3  = r2 >> 1;
    int t   = r3 % 9;
    int cv  = r3 / 9;
    const float* w = cv ? w2 : w1;
    float v = w[oc * 576 + (c2 * 32 + ch5) * 9 + t];
    __nv_bfloat16 hi = __float2bfloat16(v);
    __nv_bfloat16 lo = __float2bfloat16(v - __bfloat162float(hi));
    __nv_bfloat16* dst = g_Wpack + (size_t)r * 64;
    dst[ch5]      = hi;
    dst[32 + ch5] = lo;
}

// ---------------- tensor-core 3x3 conv (dual-bf16, reflect pad) -------------
#define PK 72
#define WOFF_B 56160
#define WB_B   9216
#define CONV_SMEM (56160 + 2 * WB_B)   // 74592

template <bool IS_CONV2>
__global__ __launch_bounds__(256)
void conv_mma_kernel(const float* __restrict__ in,
                     const __nv_bfloat16* __restrict__ wpack,
                     const float* __restrict__ bias,
                     const float* __restrict__ prelu_a,
                     float* __restrict__ out)
{
    extern __shared__ char smem[];
    __nv_bfloat16* slab = (__nv_bfloat16*)smem;            // 390 rows x PK
    float* st = (float*)smem;                              // epilogue reuse
    __nv_bfloat16* wbuf[2] = { (__nv_bfloat16*)(smem + WOFF_B),
                               (__nv_bfloat16*)(smem + WOFF_B + WB_B) };
    __shared__ float sbias[64], sact[64];

    const int tid  = threadIdx.x;
    const int lane = tid & 31;
    const int wid  = tid >> 5;
    const int wm   = wid & 3;
    const int wn   = wid >> 2;
    const int x0   = blockIdx.x * 128;
    const int y0   = blockIdx.y;
    const int b    = blockIdx.z;

    if (tid < 64) { sbias[tid] = bias[tid]; sact[tid] = IS_CONV2 ? 0.f : prelu_a[tid]; }

    float acc[2][4][4];
#pragma unroll
    for (int f = 0; f < 2; f++)
#pragma unroll
        for (int g = 0; g < 4; g++)
#pragma unroll
            for (int c = 0; c < 4; c++) acc[f][g][c] = 0.0f;

    const uint32_t slab_u = s2u(slab);
    const uint32_t wu[2]  = { s2u(wbuf[0]), s2u(wbuf[1]) };

    // per-thread ldmatrix bases
    const int arow  = wm * 32 + (lane & 15);
    const int acol  = (lane >> 4) << 3;
    const uint32_t abase = slab_u + (uint32_t)((arow * PK + acol) * 2);
    const int bg    = lane >> 4;             // n-tile select within x4
    const int bk    = ((lane >> 3) & 1) << 3;
    const int blrow = lane & 7;

    for (int c2 = 0; c2 < 2; c2++) {
        __syncthreads();
        // ---- stage input slab: 32 ch x (3 rows x 130 px), hi/lo split ----
        const float* src = in + ((size_t)(b * CH + c2 * 32)) * HWN;
        for (int idx = tid; idx < 3072; idx += 256) {
            int ch  = idx / 96;
            int rem = idx - ch * 96;
            int r3  = rem >> 5;
            int v   = rem & 31;
            int ry  = reflect(y0 + r3 - 1, IMG_H);
            float4 f4 = *(const float4*)&src[(size_t)ch * HWN + ry * IMG_W + x0 + 4 * v];
            int row = r3 * 130 + 1 + 4 * v;
            float vals[4] = { f4.x, f4.y, f4.z, f4.w };
#pragma unroll
            for (int e = 0; e < 4; e++) {
                __nv_bfloat16 hi = __float2bfloat16(vals[e]);
                slab[(row + e) * PK + ch]      = hi;
                slab[(row + e) * PK + 32 + ch] = __float2bfloat16(vals[e] - __bfloat162float(hi));
            }
        }
        if (tid < 192) {  // halo edges
            int ch = tid / 6, rem = tid % 6;
            int r3 = rem >> 1, e = rem & 1;
            int ry = reflect(y0 + r3 - 1, IMG_H);
            int gx = e ? reflect(x0 + 128, IMG_W) : reflect(x0 - 1, IMG_W);
            float v = src[(size_t)ch * HWN + ry * IMG_W + gx];
            int row = r3 * 130 + (e ? 129 : 0);
            __nv_bfloat16 hi = __float2bfloat16(v);
            slab[row * PK + ch]      = hi;
            slab[row * PK + 32 + ch] = __float2bfloat16(v - __bfloat162float(hi));
        }
        // stage tap-0 weights into buf 0
        {
            const __nv_bfloat16* wsrc = wpack + (((size_t)0 * 2 + c2) << 12);
#pragma unroll
            for (int k = 0; k < 2; k++) {
                int idx = tid + k * 256;
                int oc = idx >> 3, kb = (idx & 7) << 3;
                *(uint4*)(wbuf[0] + oc * PK + kb) = *(const uint4*)(wsrc + oc * 64 + kb);
            }
        }

#pragma unroll
        for (int t = 0; t < 9; t++) {
            __syncthreads();
            if (t < 8) {   // prefetch next tap into the other buffer
                const __nv_bfloat16* wsrc = wpack + (((size_t)(t + 1) * 2 + c2) << 12);
                __nv_bfloat16* dst = wbuf[(t + 1) & 1];
#pragma unroll
                for (int k = 0; k < 2; k++) {
                    int idx = tid + k * 256;
                    int oc = idx >> 3, kb = (idx & 7) << 3;
                    *(uint4*)(dst + oc * PK + kb) = *(const uint4*)(wsrc + oc * 64 + kb);
                }
            }
            const uint32_t wbu = wu[t & 1];
            const int rowbase = (t / 3) * 130 + (t % 3);

#pragma unroll
            for (int ks = 0; ks < 32; ks += 16) {
                uint32_t ah[2][4], al[2][4];
#pragma unroll
                for (int f = 0; f < 2; f++) {
                    uint32_t ad = abase + (uint32_t)(((rowbase + f * 16) * PK + ks) * 2);
                    ldsm_x4(ad,      ah[f][0], ah[f][1], ah[f][2], ah[f][3]);
                    ldsm_x4(ad + 64, al[f][0], al[f][1], al[f][2], al[f][3]);
                }
#pragma unroll
                for (int gp = 0; gp < 2; gp++) {
                    int brow = wn * 32 + (2 * gp + bg) * 8 + blrow;
                    uint32_t bb = wbu + (uint32_t)((brow * PK + bk + ks) * 2);
                    uint32_t bh0, bh1, bh2, bh3, bl0, bl1, bl2, bl3;
                    ldsm_x4(bb,      bh0, bh1, bh2, bh3);
                    ldsm_x4(bb + 64, bl0, bl1, bl2, bl3);
#pragma unroll
                    for (int f = 0; f < 2; f++) {
                        mma16816(acc[f][2 * gp],     ah[f], bh0, bh1);
                        mma16816(acc[f][2 * gp],     al[f], bh0, bh1);
                        mma16816(acc[f][2 * gp],     ah[f], bl0, bl1);
                        mma16816(acc[f][2 * gp + 1], ah[f], bh2, bh3);
                        mma16816(acc[f][2 * gp + 1], al[f], bh2, bh3);
                        mma16816(acc[f][2 * gp + 1], ah[f], bl2, bl3);
                    }
                }
            }
        }
    }

    // ---- epilogue: transpose via smem, fused stats ----
    __syncthreads();
#pragma unroll
    for (int f = 0; f < 2; f++)
#pragma unroll
        for (int g = 0; g < 4; g++)
#pragma unroll
            for (int c = 0; c < 4; c++) {
                int m = wm * 32 + f * 16 + (lane >> 2) + ((c >> 1) << 3);
                int n = wn * 32 + g * 8 + ((lane & 3) << 1) + (c & 1);
                st[n * 130 + m] = acc[f][g][c] + sbias[n];
            }
    __syncthreads();

    const size_t obase = (size_t)b * CH * HWN + (size_t)y0 * IMG_W + x0;
    if (!IS_CONV2) {
        for (int j = tid; j < 8192; j += 256) {
            int oc = j >> 7, p = j & 127;
            float v = st[oc * 130 + p];
            v = v > 0.0f ? v : sact[oc] * v;
            out[obase + (size_t)oc * HWN + p] = v;
        }
    } else {
        for (int j = tid; j < 8192; j += 256) {
            int oc = j >> 7, p = j & 127;
            out[obase + (size_t)oc * HWN + p] = st[oc * 130 + p];
        }
        if (tid < 128) {
            int p = tid;
            float s = 0.0f, mx = -FLT_MAX;
#pragma unroll 8
            for (int oc = 0; oc < 64; oc++) {
                float v = st[oc * 130 + p];
                s += v; mx = fmaxf(mx, v);
            }
            g_avg[b * HWN + y0 * IMG_W + x0 + p] = s * (1.0f / CH);
            g_max[b * HWN + y0 * IMG_W + x0 + p] = mx;
        } else if (tid < 192) {
            int oc = tid - 128;
            float s = 0.0f;
#pragma unroll 8
            for (int p = 0; p < 128; p++) s += st[oc * 130 + p];
            atomicAdd(&g_chansum[b * CH + oc], s);
        }
    }
}

// ---------------- spatial attention conv (2ch -> 1ch, sigmoid) -------------
__global__ __launch_bounds__(256)
void sa_kernel(const float* __restrict__ sa_w, const float* __restrict__ sa_b)
{
    int p = blockIdx.x * 256 + threadIdx.x;
    int b = blockIdx.y;
    int x = p & (IMG_W - 1);
    int y = p >> 8;
    float s = sa_b[0];
#pragma unroll
    for (int ky = 0; ky < 3; ky++) {
        int gy = reflect(y + ky - 1, IMG_H);
#pragma unroll
        for (int kx = 0; kx < 3; kx++) {
            int gx = reflect(x + kx - 1, IMG_W);
            int q = b * HWN + gy * IMG_W + gx;
            s = fmaf(sa_w[ky * 3 + kx],     g_avg[q], s);
            s = fmaf(sa_w[9 + ky * 3 + kx], g_max[q], s);
        }
    }
    g_sg[b * HWN + p] = 1.0f / (1.0f + expf(-s));
}

// ---------------- per-batch small dense math + K prepack --------------------
__global__ __launch_bounds__(256)
void small_kernel(const float* __restrict__ h_in,
                  const float* __restrict__ ca_w1, const float* __restrict__ ca_b1,
                  const float* __restrict__ ca_a,
                  const float* __restrict__ ca_w2, const float* __restrict__ ca_b2,
                  const float* __restrict__ fc_w,  const float* __restrict__ fc_b,
                  const float* __restrict__ k1_w,  const float* __restrict__ k1_b,
                  const float* __restrict__ k2_w,  const float* __restrict__ k2_b,
                  const float* __restrict__ k3_w,  const float* __restrict__ k3_b)
{
    __shared__ float g[64], t1[32], cv[64], hv[16], t0[16], ta[32], tb[32];
    const int b = blockIdx.x;
    const int tid = threadIdx.x;

    if (tid < 64) g[tid] = g_chansum[b * CH + tid] * (1.0f / HWN);
    if (tid < 16) hv[tid] = h_in[b * 16 + tid];
    __syncthreads();

    if (tid < 32) {
        float s = ca_b1[tid];
        for (int c = 0; c < 64; c++) s = fmaf(ca_w1[tid * 64 + c], g[c], s);
        t1[tid] = s > 0.0f ? s : ca_a[tid] * s;
    }
    if (tid >= 32 && tid < 48) {
        int j = tid - 32;
        float s = fc_b[j];
        for (int c = 0; c < 16; c++) s = fmaf(fc_w[j * 16 + c], hv[c], s);
        t0[j] = s >= 0.0f ? s : 0.01f * s;
    }
    __syncthreads();

    if (tid < 64) {
        float s = ca_b2[tid];
        for (int j = 0; j < 32; j++) s = fmaf(ca_w2[tid * 32 + j], t1[j], s);
        cv[tid] = 1.0f / (1.0f + expf(-s));
    }
    if (tid >= 64 && tid < 96) {
        int j = tid - 64;
        float s = k1_b[j];
        for (int c = 0; c < 16; c++) s = fmaf(k1_w[j * 16 + c], t0[c], s);
        ta[j] = s >= 0.0f ? s : 0.01f * s;
    }
    __syncthreads();

    if (tid < 32) {
        float s = k2_b[tid];
        for (int j = 0; j < 32; j++) s = fmaf(k2_w[tid * 32 + j], ta[j], s);
        tb[tid] = s >= 0.0f ? s : 0.01f * s;
    }
    __syncthreads();

    for (int idx = tid; idx < 8192; idx += 256) {
        float s = k3_b[idx];
        for (int j = 0; j < 32; j++) s = fmaf(k3_w[idx * 32 + j], tb[j], s);
        int o = idx >> 7, i = idx & 127;
        int which = (i >= 64);
        int ch = i & 63;
        float val = which ? s * cv[ch] : s;
        __nv_bfloat16 hi = __float2bfloat16(val);
        __nv_bfloat16 lo = __float2bfloat16(val - __bfloat162float(hi));
        size_t base = (size_t)b * 16384 + (which * 64 + o) * 128 + ch;
        g_Kpk[base]      = hi;
        g_Kpk[base + 64] = lo;
    }
}

// ---------------- final: tensor-core dual matvec + residual ------------------
#define PF  136
#define STP 132
#define KM_B   34816
#define SLR_B  34816
#define FIN_SMEM (KM_B + SLR_B + 512)   // 70144

__global__ __launch_bounds__(256)
void final_kernel(const float* __restrict__ hc_bias,
                  const float* __restrict__ x,
                  float* __restrict__ out)
{
    extern __shared__ char smem[];
    __nv_bfloat16* sKm   = (__nv_bfloat16*)smem;              // [128 rows][PF]
    __nv_bfloat16* slabR = (__nv_bfloat16*)(smem + KM_B);     // [128 px][PF]
    float* ssg = (float*)(smem + KM_B + SLR_B);               // [128]
    float* st  = (float*)smem;                                // epilogue reuse
    __shared__ float sbias[64];

    const int tid  = threadIdx.x;
    const int lane = tid & 31;
    const int wid  = tid >> 5;
    const int wm   = wid & 3;
    const int wn   = wid >> 2;
    const int b    = blockIdx.y;
    const int p0   = blockIdx.x * 128;

    if (tid < 64) sbias[tid] = hc_bias[tid];
    // stage K matrices
    const __nv_bfloat16* ksrc = g_Kpk + (size_t)b * 16384;
    for (int idx = tid; idx < 2048; idx += 256) {
        int r = idx >> 4, v = (idx & 15) << 3;
        *(uint4*)(sKm + r * PF + v) = *(const uint4*)(ksrc + r * 128 + v);
    }
    // stage r slab (transpose + hi/lo split)
    for (int idx = tid; idx < 2048; idx += 256) {
        int ch = idx >> 5, v = idx & 31;
        float4 f4 = *(const float4*)&g_r[((size_t)(b * CH + ch)) * HWN + p0 + 4 * v];
        float vals[4] = { f4.x, f4.y, f4.z, f4.w };
#pragma unroll
        for (int e = 0; e < 4; e++) {
            int px = 4 * v + e;
            __nv_bfloat16 hi = __float2bfloat16(vals[e]);
            slabR[px * PF + ch]      = hi;
            slabR[px * PF + 64 + ch] = __float2bfloat16(vals[e] - __bfloat162float(hi));
        }
    }
    if (tid < 128) ssg[tid] = g_sg[b * HWN + p0 + tid];
    __syncthreads();

    const uint32_t km_u = s2u(sKm);
    const uint32_t sr_u = s2u(slabR);
    const int acol  = (lane >> 4) << 3;
    const uint32_t abase = sr_u + (uint32_t)(((wm * 32 + (lane & 15)) * PF + acol) * 2);
    const int bg    = lane >> 4;
    const int bk    = ((lane >> 3) & 1) << 3;
    const int blrow = lane & 7;

    float acc[2][2][4][4];
#pragma unroll
    for (int s = 0; s < 2; s++)
#pragma unroll
        for (int f = 0; f < 2; f++)
#pragma unroll
            for (int g = 0; g < 4; g++)
#pragma unroll
                for (int c = 0; c < 4; c++) acc[s][f][g][c] = 0.0f;

#pragma unroll
    for (int ks = 0; ks < 4; ks++) {
        uint32_t ah[2][4], al[2][4];
#pragma unroll
        for (int f = 0; f < 2; f++) {
            uint32_t ad = abase + (uint32_t)(((f * 16) * PF + ks * 16) * 2);
            ldsm_x4(ad,       ah[f][0], ah[f][1], ah[f][2], ah[f][3]);
            ldsm_x4(ad + 128, al[f][0], al[f][1], al[f][2], al[f][3]);
        }
#pragma unroll
        for (int s = 0; s < 2; s++) {
#pragma unroll
            for (int gp = 0; gp < 2; gp++) {
                int brow = s * 64 + wn * 32 + (2 * gp + bg) * 8 + blrow;
                uint32_t bb = km_u + (uint32_t)((brow * PF + bk + ks * 16) * 2);
                uint32_t bh0, bh1, bh2, bh3, bl0, bl1, bl2, bl3;
                ldsm_x4(bb,       bh0, bh1, bh2, bh3);
                ldsm_x4(bb + 128, bl0, bl1, bl2, bl3);
#pragma unroll
                for (int f = 0; f < 2; f++) {
                    mma16816(acc[s][f][2 * gp],     ah[f], bh0, bh1);
                    mma16816(acc[s][f][2 * gp],     al[f], bh0, bh1);
                    mma16816(acc[s][f][2 * gp],     ah[f], bl0, bl1);
                    mma16816(acc[s][f][2 * gp + 1], ah[f], bh2, bh3);
                    mma16816(acc[s][f][2 * gp + 1], al[f], bh2, bh3);
                    mma16816(acc[s][f][2 * gp + 1], ah[f], bl2, bl3);
                }
            }
        }
    }

    // fold sg + bias, transpose via smem
    float sgv[2][2];   // sg for the two m rows per (f, c>>1)
    __syncthreads();   // done reading slabR/sKm before st overwrite? st aliases sKm region.
    // NOTE: must read ssg before overwriting? ssg lives past st region (offset 69632) - safe.
#pragma unroll
    for (int f = 0; f < 2; f++)
#pragma unroll
        for (int g = 0; g < 4; g++)
#pragma unroll
            for (int c = 0; c < 4; c++) {
                int m = wm * 32 + f * 16 + (lane >> 2) + ((c >> 1) << 3);
                int n = wn * 32 + g * 8 + ((lane & 3) << 1) + (c & 1);
                st[n * STP + m] = ssg[m] * acc[0][f][g][c] + acc[1][f][g][c] + sbias[n];
            }
    __syncthreads();

    const size_t obase = (size_t)b * CH * HWN + p0;
    for (int idx = tid; idx < 2048; idx += 256) {
        int oc = idx >> 5, v = (idx & 31) << 2;
        size_t gi = obase + (size_t)oc * HWN + v;
        float4 xv = *(const float4*)&x[gi];
        float4 sv = *(const float4*)&st[oc * STP + v];
        float4 ov = { xv.x + sv.x, xv.y + sv.y, xv.z + sv.z, xv.w + sv.w };
        *(float4*)&out[gi] = ov;
    }
}

// ---------------- launch ----------------------------------------------------
extern "C" void kernel_launch(void* const* d_in, const int* in_sizes, int n_in,
                              void* d_out, int out_size)
{
    const float* x       = (const float*)d_in[0];
    const float* h       = (const float*)d_in[1];
    const float* conv1_w = (const float*)d_in[2];
    const float* conv1_b = (const float*)d_in[3];
    const float* prelu_a = (const float*)d_in[4];
    const float* conv2_w = (const float*)d_in[5];
    const float* conv2_b = (const float*)d_in[6];
    const float* sa_w    = (const float*)d_in[7];
    const float* sa_b    = (const float*)d_in[8];
    const float* ca_w1   = (const float*)d_in[9];
    const float* ca_b1   = (const float*)d_in[10];
    const float* ca_a    = (const float*)d_in[11];
    const float* ca_w2   = (const float*)d_in[12];
    const float* ca_b2   = (const float*)d_in[13];
    const float* fc_w    = (const float*)d_in[14];
    const float* fc_b    = (const float*)d_in[15];
    const float* k1_w    = (const float*)d_in[16];
    const float* k1_b    = (const float*)d_in[17];
    const float* k2_w    = (const float*)d_in[18];
    const float* k2_b    = (const float*)d_in[19];
    const float* k3_w    = (const float*)d_in[20];
    const float* k3_b    = (const float*)d_in[21];
    const float* hc_bias = (const float*)d_in[22];
    float* out = (float*)d_out;

    float* r1 = nullptr;
    float* r  = nullptr;
    __nv_bfloat16* wpk = nullptr;
    cudaGetSymbolAddress((void**)&r1,  g_r1);
    cudaGetSymbolAddress((void**)&r,   g_r);
    cudaGetSymbolAddress((void**)&wpk, g_Wpack);

    static bool attr_set = false;
    if (!attr_set) {
        cudaFuncSetAttribute(conv_mma_kernel<false>,
                             cudaFuncAttributeMaxDynamicSharedMemorySize, CONV_SMEM);
        cudaFuncSetAttribute(conv_mma_kernel<true>,
                             cudaFuncAttributeMaxDynamicSharedMemorySize, CONV_SMEM);
        cudaFuncSetAttribute(final_kernel,
                             cudaFuncAttributeMaxDynamicSharedMemorySize, FIN_SMEM);
        attr_set = true;
    }

    init_kernel<<<2, 256>>>();
    wpack_kernel<<<288, 256>>>(conv1_w, conv2_w);

    dim3 cgrid(IMG_W / 128, IMG_H, NB);
    conv_mma_kernel<false><<<cgrid, 256, CONV_SMEM>>>(x,  wpk,         conv1_b, prelu_a, r1);
    conv_mma_kernel<true ><<<cgrid, 256, CONV_SMEM>>>(r1, wpk + 73728, conv2_b, prelu_a, r);

    sa_kernel<<<dim3(HWN / 256, NB), 256>>>(sa_w, sa_b);

    small_kernel<<<NB, 256>>>(h, ca_w1, ca_b1, ca_a, ca_w2, ca_b2,
                              fc_w, fc_b, k1_w, k1_b, k2_w, k2_b, k3_w, k3_b);

    final_kernel<<<dim3(HWN / 128, NB), 256, FIN_SMEM>>>(hc_bias, x, out);
}